// round 3
// baseline (speedup 1.0000x reference)
#include <cuda_runtime.h>
#include <math_constants.h>

// Problem constants
#define HH 224
#define WW 224
#define CC 1024
#define BB 256
#define EPS_F 0.001f
#define NUMPIX 50176.0f

// Tiling
#define CTILE 64
#define NCBLK (CC / CTILE)      // 16
#define HCHUNK 8
#define NCHUNK (HH / HCHUNK)    // 28
#define WPT 28                  // f32x2 w-pairs per thread (56 w values)

// Scratch tables (allocation-free: device globals)
// g_Ex blocked layout: float2 pair for (c, wpair) at
//   u64 index (cblk*112 + wp)*64 + cmod   (cblk=c/64, cmod=c%64, wp=w/2)
__device__ __align__(16) float g_Ex[CC * WW];
// g_EyT[h][c] = exp(-(y_h - p0)^2 / ts2) * factor * cw / (H*W)
__device__ __align__(16) float g_EyT[HH * CC];

// ---------------- packed f32x2 helpers (FFMA2 — full-rate fp32) ------------
__device__ __forceinline__ void ffma2(unsigned long long& d,
                                      unsigned long long a,
                                      unsigned long long b) {
    asm("fma.rn.f32x2 %0, %1, %2, %0;" : "+l"(d) : "l"(a), "l"(b));
}
__device__ __forceinline__ unsigned long long add2(unsigned long long a,
                                                   unsigned long long b) {
    unsigned long long d;
    asm("add.rn.f32x2 %0, %1, %2;" : "=l"(d) : "l"(a), "l"(b));
    return d;
}
__device__ __forceinline__ unsigned long long pack2(float f) {
    unsigned long long d;
    asm("mov.b64 %0, {%1, %1};" : "=l"(d) : "f"(f));
    return d;
}
__device__ __forceinline__ void unpack2(unsigned long long v, float& lo, float& hi) {
    asm("mov.b64 {%0, %1}, %2;" : "=f"(lo), "=f"(hi) : "l"(v));
}

// ---------------- cp.async helpers ----------------------------------------
__device__ __forceinline__ void cp_async16(void* smem_dst, const void* gmem_src) {
    unsigned s = (unsigned)__cvta_generic_to_shared(smem_dst);
    asm volatile("cp.async.cg.shared.global [%0], [%1], 16;\n" ::"r"(s), "l"(gmem_src));
}
__device__ __forceinline__ void cp_commit() {
    asm volatile("cp.async.commit_group;\n" ::: "memory");
}
__device__ __forceinline__ void cp_wait1() {
    asm volatile("cp.async.wait_group 1;\n" ::: "memory");
}

// ---------------- prep: build separable Gaussian tables --------------------
__global__ void prep_kernel(const float* __restrict__ positions,
                            const float* __restrict__ sigmas,
                            const float* __restrict__ curve_weights,
                            const float* __restrict__ xs,
                            const float* __restrict__ ys) {
    int c = blockIdx.x;      // 0..1023
    int t = threadIdx.x;     // 0..223  (= w for Ex, = h for Ey)

    float p0 = positions[2 * c];       // y-coordinate (pairs with ys)
    float p1 = positions[2 * c + 1];   // x-coordinate (pairs with xs)
    float s  = sigmas[c];
    float cw = curve_weights[c];

    float s2     = s * s;
    float ts2    = 2.0f * s2 + EPS_F;
    float factor = 1.0f / (2.0f * CUDART_PI_F * s2 + EPS_F);
    float fcw    = factor * cw / NUMPIX;

    // Ex[w=t, c]  (xs[i][j] = x_axis[j] -> row 0 of xs)
    float dx  = xs[t] - p1;
    float exv = expf(-(dx * dx) / ts2);
    int cblk = c >> 6, cmod = c & 63;
    int wp = t >> 1, lane = t & 1;
    g_Ex[(((cblk * 112 + wp) * 64) + cmod) * 2 + lane] = exv;

    // Ey[h=t, c] * factor * cw / numpix   (ys[i][j] = y_axis[i] -> column 0)
    float dy = ys[t * WW] - p0;
    g_EyT[t * CC + c] = expf(-(dy * dy) / ts2) * fcw;
}

// ---------------- fused separable GEMM -------------------------------------
// out[b, cblk*64 + c] = sum_h Eyf[h,c] * sum_w x[b,h,w] * Ex[w,c]
// Thread layout: c = tid & 63, wg = tid >> 6 (w in [wg*56, wg*56+56)).
// Ex pairs live in registers for the whole kernel; x streamed through smem.
__global__ void __launch_bounds__(256, 2)
blob_gemm_kernel(const float* __restrict__ x, float* __restrict__ out) {
    __shared__ __align__(16) float xs_s[2][HCHUNK][WW];   // 2 x 7KB
    __shared__ float red[256];

    const int tid  = threadIdx.x;
    const int c    = tid & 63;
    const int wg   = tid >> 6;
    const int cblk = blockIdx.x;
    const int b    = blockIdx.y;

    const float* xb = x + (size_t)b * (HH * WW);

    // Fill Ex register file: 28 f32x2 pairs, fully coalesced (lanes = consecutive c)
    unsigned long long ex[WPT];
    {
        const unsigned long long* exg =
            reinterpret_cast<const unsigned long long*>(g_Ex) +
            (cblk * 112 + wg * WPT) * 64 + c;
#pragma unroll
        for (int k = 0; k < WPT; k++) ex[k] = exg[k * 64];
    }

    const float* eyg = g_EyT + cblk * CTILE + c;

    unsigned long long acc = 0ull;

    float eycur[HCHUNK], eynxt[HCHUNK];
#pragma unroll
    for (int i = 0; i < HCHUNK; i++) eycur[i] = eyg[i * CC];

    // Prologue: stage chunk 0 (8 rows = 448 x 16B)
    {
        float* dst = &xs_s[0][0][0];
        cp_async16(dst + tid * 4, xb + tid * 4);
        if (tid < 192) cp_async16(dst + (tid + 256) * 4, xb + (tid + 256) * 4);
        cp_commit();
    }

    for (int chunk = 0; chunk < NCHUNK; chunk++) {
        const int buf = chunk & 1;

        // Stage next chunk into the other buffer
        if (chunk + 1 < NCHUNK) {
            const float* src = xb + (chunk + 1) * HCHUNK * WW;
            float* dst = &xs_s[buf ^ 1][0][0];
            cp_async16(dst + tid * 4, src + tid * 4);
            if (tid < 192) cp_async16(dst + (tid + 256) * 4, src + (tid + 256) * 4);
        }
        cp_commit();
        cp_wait1();          // current chunk's group complete; next may fly
        __syncthreads();

        // Prefetch next chunk's Ey values (L2 hits) into registers
        if (chunk + 1 < NCHUNK) {
#pragma unroll
            for (int i = 0; i < HCHUNK; i++)
                eynxt[i] = eyg[((chunk + 1) * HCHUNK + i) * CC];
        }

        // Compute 8 rows
#pragma unroll
        for (int hh = 0; hh < HCHUNK; hh++) {
            const ulonglong2* xrow =
                reinterpret_cast<const ulonglong2*>(&xs_s[buf][hh][wg * 56]);
            unsigned long long t0 = 0ull, t1 = 0ull, t2 = 0ull, t3 = 0ull;
#pragma unroll
            for (int k = 0; k < 14; k += 2) {
                ulonglong2 xv0 = xrow[k];
                ffma2(t0, xv0.x, ex[2 * k]);
                ffma2(t1, xv0.y, ex[2 * k + 1]);
                ulonglong2 xv1 = xrow[k + 1];
                ffma2(t2, xv1.x, ex[2 * k + 2]);
                ffma2(t3, xv1.y, ex[2 * k + 3]);
            }
            unsigned long long ts = add2(add2(t0, t1), add2(t2, t3));
            unsigned long long ey2 = pack2(eycur[hh]);
            ffma2(acc, ts, ey2);
        }
        __syncthreads();     // everyone done reading buf before it is re-staged

#pragma unroll
        for (int i = 0; i < HCHUNK; i++) eycur[i] = eynxt[i];
    }

    // Reduce the 4 w-group partials per channel
    float lo, hi;
    unpack2(acc, lo, hi);
    red[tid] = lo + hi;
    __syncthreads();
    if (tid < CTILE) {
        float s = red[tid] + red[tid + 64] + red[tid + 128] + red[tid + 192];
        out[b * CC + cblk * CTILE + tid] = s;
    }
}

// ---------------- launch ----------------------------------------------------
extern "C" void kernel_launch(void* const* d_in, const int* in_sizes, int n_in,
                              void* d_out, int out_size) {
    const float* x   = (const float*)d_in[0];
    const float* pos = (const float*)d_in[1];
    const float* sig = (const float*)d_in[2];
    const float* cwt = (const float*)d_in[3];
    const float* xs  = (const float*)d_in[4];
    const float* ys  = (const float*)d_in[5];
    float* out = (float*)d_out;

    prep_kernel<<<CC, HH>>>(pos, sig, cwt, xs, ys);

    dim3 grid(NCBLK, BB);
    blob_gemm_kernel<<<grid, 256>>>(x, out);
}

// round 4
// speedup vs baseline: 1.2558x; 1.2558x over previous
#include <cuda_runtime.h>
#include <math_constants.h>

// Problem constants
#define HH 224
#define WW 224
#define CC 1024
#define BB 256
#define EPS_F 0.001f
#define NUMPIX 50176.0f

// Tiling: block = 256 threads = 8 w-groups (1 per warp) x 32 c-lanes.
// Each thread owns 2 channels (clane, clane+32) and 28 w values (14 f32x2 pairs).
#define CTILE 64
#define NCBLK (CC / CTILE)      // 16
#define HCHUNK 8
#define NCHUNK (HH / HCHUNK)    // 28
#define KPT 14                  // f32x2 w-pairs per thread per channel (28 w)

// Scratch tables (allocation-free: device globals)
// g_Ex blocked layout (u64/f32x2 units):
//   idx = ((cblk*8 + wg)*14 + k)*64 + csub*32 + clane
//   where c = cblk*64 + csub*32 + clane, w = wg*28 + 2k (+lane)
__device__ __align__(16) float g_Ex[CC * WW];
// g_EyT[h][c] = exp(-(y_h - p0)^2 / ts2) * factor * cw / (H*W)
__device__ __align__(16) float g_EyT[HH * CC];

// ---------------- packed f32x2 helpers (FFMA2 — full-rate fp32) ------------
__device__ __forceinline__ void ffma2(unsigned long long& d,
                                      unsigned long long a,
                                      unsigned long long b) {
    asm("fma.rn.f32x2 %0, %1, %2, %0;" : "+l"(d) : "l"(a), "l"(b));
}
__device__ __forceinline__ unsigned long long add2(unsigned long long a,
                                                   unsigned long long b) {
    unsigned long long d;
    asm("add.rn.f32x2 %0, %1, %2;" : "=l"(d) : "l"(a), "l"(b));
    return d;
}
__device__ __forceinline__ unsigned long long pack2(float f) {
    unsigned long long d;
    asm("mov.b64 %0, {%1, %1};" : "=l"(d) : "f"(f));
    return d;
}
__device__ __forceinline__ void unpack2(unsigned long long v, float& lo, float& hi) {
    asm("mov.b64 {%0, %1}, %2;" : "=f"(lo), "=f"(hi) : "l"(v));
}

// ---------------- cp.async helpers ----------------------------------------
__device__ __forceinline__ void cp_async16(void* smem_dst, const void* gmem_src) {
    unsigned s = (unsigned)__cvta_generic_to_shared(smem_dst);
    asm volatile("cp.async.cg.shared.global [%0], [%1], 16;\n" ::"r"(s), "l"(gmem_src));
}
__device__ __forceinline__ void cp_commit() {
    asm volatile("cp.async.commit_group;\n" ::: "memory");
}
__device__ __forceinline__ void cp_wait1() {
    asm volatile("cp.async.wait_group 1;\n" ::: "memory");
}

// ---------------- prep: build separable Gaussian tables --------------------
__global__ void prep_kernel(const float* __restrict__ positions,
                            const float* __restrict__ sigmas,
                            const float* __restrict__ curve_weights,
                            const float* __restrict__ xs,
                            const float* __restrict__ ys) {
    int c = blockIdx.x;      // 0..1023
    int t = threadIdx.x;     // 0..223  (= w for Ex, = h for Ey)

    float p0 = positions[2 * c];       // y-coordinate (pairs with ys)
    float p1 = positions[2 * c + 1];   // x-coordinate (pairs with xs)
    float s  = sigmas[c];
    float cw = curve_weights[c];

    float s2     = s * s;
    float ts2    = 2.0f * s2 + EPS_F;
    float factor = 1.0f / (2.0f * CUDART_PI_F * s2 + EPS_F);
    float fcw    = factor * cw / NUMPIX;

    // Ex[w=t, c]  (xs[i][j] = x_axis[j] -> row 0 of xs)
    float dx  = xs[t] - p1;
    float exv = expf(-(dx * dx) / ts2);
    int cblk = c >> 6, cm = c & 63, csub = cm >> 5, clane = cm & 31;
    int wp = t >> 1, wg = wp / KPT, k = wp - wg * KPT, lane = t & 1;
    g_Ex[((((cblk * 8 + wg) * KPT + k) * 64) + csub * 32 + clane) * 2 + lane] = exv;

    // Ey[h=t, c] * factor * cw / numpix   (ys[i][j] = y_axis[i] -> column 0)
    float dy = ys[t * WW] - p0;
    g_EyT[t * CC + c] = expf(-(dy * dy) / ts2) * fcw;
}

// ---------------- fused separable GEMM -------------------------------------
// out[b, cblk*64 + csub*32 + clane] = sum_h Eyf[h,c] * sum_w x[b,h,w]*Ex[w,c]
// warp = w-group (broadcast LDS); each thread holds Ex for 2 channels so each
// LDS.128 feeds 4 FFMA2.
__global__ void __launch_bounds__(256, 2)
blob_gemm_kernel(const float* __restrict__ x, float* __restrict__ out) {
    __shared__ __align__(16) float xs_s[2][HCHUNK][WW];   // 2 x 7 KB
    __shared__ float red[512];

    const int tid   = threadIdx.x;
    const int clane = tid & 31;
    const int wg    = tid >> 5;        // warp index == w-group (broadcast LDS)
    const int cblk  = blockIdx.x;
    const int b     = blockIdx.y;

    const float* xb = x + (size_t)b * (HH * WW);

    // Fill Ex register file: 14 pairs per channel, 2 channels. Coalesced loads
    // (lanes = consecutive clane -> contiguous 256B per k).
    unsigned long long ex0[KPT], ex1[KPT];
    {
        const unsigned long long* exg =
            reinterpret_cast<const unsigned long long*>(g_Ex) +
            ((cblk * 8 + wg) * KPT) * 64 + clane;
#pragma unroll
        for (int k = 0; k < KPT; k++) {
            ex0[k] = exg[k * 64];
            ex1[k] = exg[k * 64 + 32];
        }
    }

    const float* ey0g = g_EyT + cblk * CTILE + clane;        // channel c0
    const float* ey1g = ey0g + 32;                           // channel c1

    unsigned long long acc0 = 0ull, acc1 = 0ull;

    // Prologue: stage chunk 0 (8 rows = 448 x 16B)
    {
        float* dst = &xs_s[0][0][0];
        cp_async16(dst + tid * 4, xb + tid * 4);
        if (tid < 192) cp_async16(dst + (tid + 256) * 4, xb + (tid + 256) * 4);
        cp_commit();
    }

    for (int chunk = 0; chunk < NCHUNK; chunk++) {
        const int buf = chunk & 1;

        // Stage next chunk into the other buffer
        if (chunk + 1 < NCHUNK) {
            const float* src = xb + (chunk + 1) * HCHUNK * WW;
            float* dst = &xs_s[buf ^ 1][0][0];
            cp_async16(dst + tid * 4, src + tid * 4);
            if (tid < 192) cp_async16(dst + (tid + 256) * 4, src + (tid + 256) * 4);
        }
        cp_commit();
        cp_wait1();          // current chunk's group complete; next may fly
        __syncthreads();

        // Ey for this chunk's 8 rows, both channels (L1/L2 hits, coalesced)
        float ey0[HCHUNK], ey1[HCHUNK];
#pragma unroll
        for (int i = 0; i < HCHUNK; i++) {
            ey0[i] = __ldg(ey0g + (chunk * HCHUNK + i) * CC);
            ey1[i] = __ldg(ey1g + (chunk * HCHUNK + i) * CC);
        }

        // Compute 8 rows: per h, 7 broadcast LDS.128 + 28 FFMA2
#pragma unroll
        for (int hh = 0; hh < HCHUNK; hh++) {
            const ulonglong2* xrow =
                reinterpret_cast<const ulonglong2*>(&xs_s[buf][hh][wg * 28]);
            unsigned long long t0 = 0ull, t1 = 0ull, t2 = 0ull, t3 = 0ull;
#pragma unroll
            for (int j = 0; j < 7; j++) {
                ulonglong2 xv = xrow[j];
                ffma2(t0, xv.x, ex0[2 * j]);
                ffma2(t1, xv.y, ex0[2 * j + 1]);
                ffma2(t2, xv.x, ex1[2 * j]);
                ffma2(t3, xv.y, ex1[2 * j + 1]);
            }
            unsigned long long s0 = add2(t0, t1);
            unsigned long long s1 = add2(t2, t3);
            ffma2(acc0, s0, pack2(ey0[hh]));
            ffma2(acc1, s1, pack2(ey1[hh]));
        }
        __syncthreads();     // everyone done reading buf before it is re-staged
    }

    // Reduce the 8 w-group partials per channel
    {
        float lo, hi;
        unpack2(acc0, lo, hi);
        red[wg * 32 + clane] = lo + hi;
        unpack2(acc1, lo, hi);
        red[256 + wg * 32 + clane] = lo + hi;
    }
    __syncthreads();
    if (tid < CTILE) {
        const int cs = tid >> 5, cl = tid & 31;
        float s = 0.0f;
#pragma unroll
        for (int g = 0; g < 8; g++) s += red[cs * 256 + g * 32 + cl];
        out[b * CC + cblk * CTILE + tid] = s;
    }
}

// ---------------- launch ----------------------------------------------------
extern "C" void kernel_launch(void* const* d_in, const int* in_sizes, int n_in,
                              void* d_out, int out_size) {
    const float* x   = (const float*)d_in[0];
    const float* pos = (const float*)d_in[1];
    const float* sig = (const float*)d_in[2];
    const float* cwt = (const float*)d_in[3];
    const float* xs  = (const float*)d_in[4];
    const float* ys  = (const float*)d_in[5];
    float* out = (float*)d_out;

    prep_kernel<<<CC, HH>>>(pos, sig, cwt, xs, ys);

    dim3 grid(NCBLK, BB);
    blob_gemm_kernel<<<grid, 256>>>(x, out);
}

// round 8
// speedup vs baseline: 1.8136x; 1.4442x over previous
#include <cuda_runtime.h>
#include <cuda_bf16.h>
#include <math_constants.h>
#include <cstdint>
#include <cstring>

// ---------------- problem constants ----------------
#define HH 224
#define WW 224
#define CC 1024
#define BB 256
#define KK (HH * WW)            // 50176
#define EPS_F 0.001f
#define NUMPIX 50176.0f

// ---------------- tiling ----------------
#define KSPLIT 8
#define HSEG (HH / KSPLIT)      // 28 h-rows per CTA
#define KSEG (HSEG * WW)        // 6272
#define KB 16                   // k per iteration (one mma k-step)
#define WBLK (WW / KB)          // 14 k-blocks per h-row
#define NIT (KSEG / KB)         // 392 iterations
#define MT 128
#define NT 128
#define NTHREADS 512
#define LDSS 48                 // smem row stride: 32B data + 16B pad (conflict-free ldmatrix)
#define STAGE_SZ (128 * LDSS)   // 6144 B per tile per stage

// ---------------- device-global scratch (no allocs allowed) ----------------
__device__ __align__(16) __nv_bfloat16 g_xhi[(size_t)BB * KK];   // 25.7 MB
__device__ __align__(16) __nv_bfloat16 g_xlo[(size_t)BB * KK];   // 25.7 MB
__device__ __align__(16) float g_ExT[CC * WW];                   // [c][w]
__device__ __align__(16) float g_EyT[HH * CC];                   // [h][c] * factor*cw/HW
__device__ __align__(16) float g_part[KSPLIT * BB * CC];         // 8 MB partials

// ---------------- PTX helpers ----------------
__device__ __forceinline__ void cp_async16(void* smem_dst, const void* gsrc) {
    unsigned s = (unsigned)__cvta_generic_to_shared(smem_dst);
    asm volatile("cp.async.cg.shared.global [%0], [%1], 16;\n" ::"r"(s), "l"(gsrc));
}
__device__ __forceinline__ void cp_commit() {
    asm volatile("cp.async.commit_group;\n" ::: "memory");
}
__device__ __forceinline__ void cp_wait1() {
    asm volatile("cp.async.wait_group 1;\n" ::: "memory");
}
__device__ __forceinline__ void ldsm_x4(uint32_t* r, uint32_t addr) {
    asm volatile("ldmatrix.sync.aligned.m8n8.x4.shared.b16 {%0,%1,%2,%3}, [%4];"
                 : "=r"(r[0]), "=r"(r[1]), "=r"(r[2]), "=r"(r[3]) : "r"(addr));
}
__device__ __forceinline__ void mma16816(float* d, const uint32_t* a, const uint32_t* b) {
    asm volatile(
        "mma.sync.aligned.m16n8k16.row.col.f32.bf16.bf16.f32 "
        "{%0,%1,%2,%3}, {%4,%5,%6,%7}, {%8,%9}, {%0,%1,%2,%3};"
        : "+f"(d[0]), "+f"(d[1]), "+f"(d[2]), "+f"(d[3])
        : "r"(a[0]), "r"(a[1]), "r"(a[2]), "r"(a[3]), "r"(b[0]), "r"(b[1]));
}
__device__ __forceinline__ uint32_t bf2_u32(__nv_bfloat162 v) {
    uint32_t u; memcpy(&u, &v, 4); return u;
}

// ---------------- prep: split x into bf16 hi/lo ----------------------------
__global__ void xsplit_kernel(const float* __restrict__ x) {
    int i = blockIdx.x * 256 + threadIdx.x;         // BB*KK total (exact)
    float v = x[i];
    __nv_bfloat16 hi = __float2bfloat16(v);
    g_xhi[i] = hi;
    g_xlo[i] = __float2bfloat16(v - __bfloat162float(hi));
}

// ---------------- prep: separable Gaussian tables ---------------------------
__global__ void tables_kernel(const float* __restrict__ positions,
                              const float* __restrict__ sigmas,
                              const float* __restrict__ curve_weights,
                              const float* __restrict__ xs,
                              const float* __restrict__ ys) {
    int c = blockIdx.x;          // 0..1023
    int t = threadIdx.x;         // 0..223
    float p0 = positions[2 * c];
    float p1 = positions[2 * c + 1];
    float s  = sigmas[c];
    float cw = curve_weights[c];
    float s2 = s * s;
    float ts2 = 2.0f * s2 + EPS_F;
    float fcw = cw / ((2.0f * CUDART_PI_F * s2 + EPS_F) * NUMPIX);

    float dx = xs[t] - p1;                          // xs row 0 = x_axis
    g_ExT[c * WW + t] = expf(-(dx * dx) / ts2);
    float dy = ys[t * WW] - p0;                     // ys col 0 = y_axis
    g_EyT[t * CC + c] = expf(-(dy * dy) / ts2) * fcw;
}

// ---------------- main split-bf16 HMMA GEMM ---------------------------------
// grid = 128: mt = bx&1 (b-tile), nt = (bx>>1)&7 (c-tile), ks = bx>>4 (k-seg)
// NOTE: writes g_part via the device symbol directly — passing a __device__
// global's address from host code hands the kernel the HOST shadow address
// (silently writable on GB300 via ATS), which was the R6/R7 failure mode.
__global__ void __launch_bounds__(NTHREADS, 1)
gemm_kernel() {
    __shared__ __align__(16) char sAh[2][STAGE_SZ];
    __shared__ __align__(16) char sAl[2][STAGE_SZ];
    __shared__ __align__(16) char sBh[2][STAGE_SZ];
    __shared__ __align__(16) char sBl[2][STAGE_SZ];   // total 49152 B

    const int tid  = threadIdx.x;
    const int lane = tid & 31;
    const int wid  = tid >> 5;
    const int bx = blockIdx.x;
    const int mt = bx & 1, nt = (bx >> 1) & 7, ks = bx >> 4;
    const int b0 = mt * MT, c0 = nt * NT, h0 = ks * HSEG;
    const size_t kseg0 = (size_t)ks * KSEG;

    const int warp_m = wid >> 2, warp_n = wid & 3;   // 4x4 warp grid
    const int mbase = warp_m * 32, nbase = warp_n * 32;

    const uint32_t uAh = (uint32_t)__cvta_generic_to_shared(&sAh[0][0]);
    const uint32_t uAl = (uint32_t)__cvta_generic_to_shared(&sAl[0][0]);
    const uint32_t uBh = (uint32_t)__cvta_generic_to_shared(&sBh[0][0]);
    const uint32_t uBl = (uint32_t)__cvta_generic_to_shared(&sBl[0][0]);

    // ldmatrix per-lane offsets (non-trans for both A and B: both stored
    // [row][k] with k contiguous, matching the row.col fragment layouts)
    const uint32_t aoff = (uint32_t)((mbase + (lane & 15)) * LDSS + (lane >> 4) * 16);
    const uint32_t boff = (uint32_t)((nbase + (lane & 15)) * LDSS + (lane >> 4) * 16);

    // A-staging coords (tid<256 -> hi, tid>=256 -> lo; 1 x 16B chunk each)
    const int ar = (tid & 255) >> 1;
    const int ah = tid & 1;
    const __nv_bfloat16* asrc_base =
        (tid < 256 ? g_xhi : g_xlo) + (size_t)(b0 + ar) * KK + kseg0 + ah * 8;
    char* adst_base = (tid < 256 ? &sAh[0][0] : &sAl[0][0]) + ar * LDSS + ah * 16;

    // B-gen coords: thread -> (c = tid>>2, 4 w values at p = tid&3)
    const int gc = tid >> 2;
    const int gp = tid & 3;
    const float* eyp = g_EyT + c0 + gc;
    const float* exp_base = g_ExT + (size_t)(c0 + gc) * WW + gp * 4;

    float acc[2][4][4];
#pragma unroll
    for (int i = 0; i < 2; i++)
#pragma unroll
        for (int j = 0; j < 4; j++)
#pragma unroll
            for (int r = 0; r < 4; r++) acc[i][j][r] = 0.0f;

    // Prologue: stage iter 0 into stage 0
    {
        cp_async16(adst_base, asrc_base);
        cp_commit();
        float ey = eyp[(size_t)h0 * CC];
        float4 e = *(const float4*)exp_base;
        float v0 = ey * e.x, v1 = ey * e.y, v2 = ey * e.z, v3 = ey * e.w;
        __nv_bfloat162 h01 = __floats2bfloat162_rn(v0, v1);
        __nv_bfloat162 h23 = __floats2bfloat162_rn(v2, v3);
        __nv_bfloat162 l01 = __floats2bfloat162_rn(v0 - __low2float(h01), v1 - __high2float(h01));
        __nv_bfloat162 l23 = __floats2bfloat162_rn(v2 - __low2float(h23), v3 - __high2float(h23));
        *(uint2*)(&sBh[0][0] + gc * LDSS + gp * 8) = make_uint2(bf2_u32(h01), bf2_u32(h23));
        *(uint2*)(&sBl[0][0] + gc * LDSS + gp * 8) = make_uint2(bf2_u32(l01), bf2_u32(l23));
    }

#pragma unroll 2
    for (int kb = 0; kb < NIT; kb++) {
        const int s = kb & 1;

        // ---- prefetch iter kb+1 into the other stage ----
        if (kb + 1 < NIT) {
            const int ns = s ^ 1;
            cp_async16(adst_base + ns * STAGE_SZ,
                       asrc_base + (size_t)(kb + 1) * KB);
            const int hl = (kb + 1) / WBLK;
            const int wb = (kb + 1) % WBLK;
            float ey = eyp[(size_t)(h0 + hl) * CC];
            float4 e = *(const float4*)(exp_base + wb * KB);
            float v0 = ey * e.x, v1 = ey * e.y, v2 = ey * e.z, v3 = ey * e.w;
            __nv_bfloat162 h01 = __floats2bfloat162_rn(v0, v1);
            __nv_bfloat162 h23 = __floats2bfloat162_rn(v2, v3);
            __nv_bfloat162 l01 = __floats2bfloat162_rn(v0 - __low2float(h01), v1 - __high2float(h01));
            __nv_bfloat162 l23 = __floats2bfloat162_rn(v2 - __low2float(h23), v3 - __high2float(h23));
            *(uint2*)(&sBh[ns][0] + gc * LDSS + gp * 8) = make_uint2(bf2_u32(h01), bf2_u32(h23));
            *(uint2*)(&sBl[ns][0] + gc * LDSS + gp * 8) = make_uint2(bf2_u32(l01), bf2_u32(l23));
        }
        cp_commit();            // (empty group on last iter keeps wait semantics)
        cp_wait1();             // A(kb) complete; next group may fly
        __syncthreads();        // gen(kb) STS + cp.async(kb) visible to all

        // ---- compute on stage s ----
        const uint32_t so = (uint32_t)(s * STAGE_SZ);
        uint32_t aH[2][4], aL[2][4];
        ldsm_x4(aH[0], uAh + so + aoff);
        ldsm_x4(aH[1], uAh + so + aoff + 16 * LDSS);
        ldsm_x4(aL[0], uAl + so + aoff);
        ldsm_x4(aL[1], uAl + so + aoff + 16 * LDSS);

        uint32_t q[4];
        uint32_t bH[4][2], bL[4][2];
        ldsm_x4(q, uBh + so + boff);
        bH[0][0] = q[0]; bH[0][1] = q[2]; bH[1][0] = q[1]; bH[1][1] = q[3];
        ldsm_x4(q, uBh + so + boff + 16 * LDSS);
        bH[2][0] = q[0]; bH[2][1] = q[2]; bH[3][0] = q[1]; bH[3][1] = q[3];
        ldsm_x4(q, uBl + so + boff);
        bL[0][0] = q[0]; bL[0][1] = q[2]; bL[1][0] = q[1]; bL[1][1] = q[3];
        ldsm_x4(q, uBl + so + boff + 16 * LDSS);
        bL[2][0] = q[0]; bL[2][1] = q[2]; bL[3][0] = q[1]; bL[3][1] = q[3];

#pragma unroll
        for (int mf = 0; mf < 2; mf++)
#pragma unroll
            for (int nf = 0; nf < 4; nf++) {
                mma16816(acc[mf][nf], aH[mf], bH[nf]);
                mma16816(acc[mf][nf], aH[mf], bL[nf]);
                mma16816(acc[mf][nf], aL[mf], bH[nf]);
            }
        __syncthreads();        // done reading stage s before it is re-staged
    }

    // ---- epilogue: write partial tile to g_part (deterministic k-split) ----
    float* pbase = g_part + (size_t)ks * BB * CC;
#pragma unroll
    for (int mf = 0; mf < 2; mf++)
#pragma unroll
        for (int nf = 0; nf < 4; nf++)
#pragma unroll
            for (int pr = 0; pr < 2; pr++) {
                int row = b0 + mbase + mf * 16 + (lane >> 2) + pr * 8;
                int col = c0 + nbase + nf * 8 + (lane & 3) * 2;
                float2 v = make_float2(acc[mf][nf][pr * 2], acc[mf][nf][pr * 2 + 1]);
                *(float2*)&pbase[(size_t)row * CC + col] = v;
            }
}

// ---------------- reduce the 8 k-split partials -----------------------------
__global__ void reduce_kernel(float* __restrict__ out) {
    int i = blockIdx.x * 256 + threadIdx.x;    // 0..262143
    float s = 0.0f;
#pragma unroll
    for (int k = 0; k < KSPLIT; k++) s += g_part[(size_t)k * BB * CC + i];
    out[i] = s;
}

// ---------------- launch ----------------------------------------------------
extern "C" void kernel_launch(void* const* d_in, const int* in_sizes, int n_in,
                              void* d_out, int out_size) {
    const float* x   = (const float*)d_in[0];
    const float* pos = (const float*)d_in[1];
    const float* sig = (const float*)d_in[2];
    const float* cwt = (const float*)d_in[3];
    const float* xs  = (const float*)d_in[4];
    const float* ys  = (const float*)d_in[5];
    float* out = (float*)d_out;

    xsplit_kernel<<<(BB * KK) / 256, 256>>>(x);
    tables_kernel<<<CC, HH>>>(pos, sig, cwt, xs, ys);
    gemm_kernel<<<128, NTHREADS>>>();
    reduce_kernel<<<(BB * CC) / 256, 256>>>(out);
}